// round 1
// baseline (speedup 1.0000x reference)
#include <cuda_runtime.h>
#include <stdint.h>

// Problem dims (fixed by the reference):
//   x:               [64, 64, 4096]  float32
//   cache:           [128, 512, 4096] float32
//   running_seqs:    [64] int32 (arange)
//   idx_salient_row: [64, 64] int32
//   out:             [64, 512, 4096] float32
//
// out[i, r, :] = x[i, j_last, :] where j_last = last j with idx[i,j]==r,
//                else cache[running_seqs[i], r, :].

#define N_RUNNING   64
#define K_SALIENT   64
#define ROWS_PER_SEQ 512
#define HIDDEN      4096
#define VEC_PER_ROW (HIDDEN / 4)   // 1024 float4 per row

__global__ __launch_bounds__(256, 8)
void mlpcache_gather_kernel(const float4* __restrict__ x,
                            const float4* __restrict__ cache,
                            const int*    __restrict__ running_seqs,
                            const int*    __restrict__ idx_salient,
                            float4*       __restrict__ out)
{
    // One block per output row.
    const int row = blockIdx.x;            // 0 .. 64*512-1
    const int i   = row >> 9;              // sequence index
    const int r   = row & (ROWS_PER_SEQ - 1);

    // Resolve the source for this row: last j with idx[i,j] == r wins
    // (matches JAX in-order scatter-set semantics for duplicate indices).
    // 64 int loads, fully L1-broadcast across the block — negligible cost.
    const int* idx_row = idx_salient + i * K_SALIENT;
    int w = -1;
    #pragma unroll
    for (int j = 0; j < K_SALIENT; ++j) {
        if (idx_row[j] == r) w = j;
    }

    const float4* __restrict__ src;
    if (w >= 0) {
        src = x + ((size_t)(i * K_SALIENT + w)) * VEC_PER_ROW;
    } else {
        const int seq = running_seqs[i];
        src = cache + ((size_t)seq * ROWS_PER_SEQ + r) * VEC_PER_ROW;
    }
    float4* __restrict__ dst = out + (size_t)row * VEC_PER_ROW;

    // 1024 float4 per row, 256 threads -> 4 fully-coalesced 16B ops each.
    #pragma unroll
    for (int c = threadIdx.x; c < VEC_PER_ROW; c += 256) {
        dst[c] = src[c];
    }
}

extern "C" void kernel_launch(void* const* d_in, const int* in_sizes, int n_in,
                              void* d_out, int out_size)
{
    const float4* x     = (const float4*)d_in[0];
    const float4* cache = (const float4*)d_in[1];
    const int* running  = (const int*)d_in[2];
    const int* idx      = (const int*)d_in[3];
    float4* out         = (float4*)d_out;

    dim3 grid(N_RUNNING * ROWS_PER_SEQ);   // 32768 blocks
    mlpcache_gather_kernel<<<grid, 256>>>(x, cache, running, idx, out);
}

// round 2
// speedup vs baseline: 1.0223x; 1.0223x over previous
#include <cuda_runtime.h>
#include <stdint.h>

// Dims (fixed):
//   x:               [64, 64, 4096]   float32
//   cache:           [128, 512, 4096] float32
//   running_seqs:    [64] int32 (arange)
//   idx_salient_row: [64, 64] int32
//   out:             [64, 512, 4096]  float32
//
// out[i, r, :] = x[i, j_last, :] where j_last = last j with idx[i,j]==r
//                (== max matching j), else cache[running_seqs[i], r, :].

#define N_RUNNING    64
#define K_SALIENT    64
#define ROWS_PER_SEQ 512
#define HIDDEN       4096
#define VEC_PER_ROW  (HIDDEN / 4)   // 1024 float4 per row
#define THREADS      256
#define VEC_PER_THR  (VEC_PER_ROW / THREADS)  // 4

__global__ __launch_bounds__(THREADS, 8)
void mlpcache_gather_kernel(const float4* __restrict__ x,
                            const float4* __restrict__ cache,
                            const int*    __restrict__ running_seqs,
                            const int*    __restrict__ idx_salient,
                            float4*       __restrict__ out)
{
    const int row = blockIdx.x;            // 0 .. 64*512-1
    const int i   = row >> 9;              // sequence index
    const int r   = row & (ROWS_PER_SEQ - 1);

    // Parallel last-wins resolve: winner = max over j of (idx[i,j]==r ? j : -1).
    // One compare per thread (threads 0..63) + shared atomicMax, instead of a
    // 64-iteration serial scan in every warp.
    __shared__ int w_sh;
    if (threadIdx.x == 0) w_sh = -1;
    __syncthreads();
    if (threadIdx.x < K_SALIENT) {
        if (idx_salient[i * K_SALIENT + threadIdx.x] == r)
            atomicMax(&w_sh, (int)threadIdx.x);
    }
    __syncthreads();
    const int w = w_sh;

    const float4* __restrict__ src;
    if (w >= 0) {
        src = x + ((size_t)(i * K_SALIENT + w)) * VEC_PER_ROW;
    } else {
        const int seq = running_seqs[i];
        src = cache + ((size_t)seq * ROWS_PER_SEQ + r) * VEC_PER_ROW;
    }
    float4* __restrict__ dst = out + (size_t)row * VEC_PER_ROW;

    // Front-batch all 4 streaming loads (MLP=4), then 4 streaming stores.
    // .cs hints: evict-first in L2 — neither stream is reused.
    float4 v[VEC_PER_THR];
    #pragma unroll
    for (int k = 0; k < VEC_PER_THR; ++k)
        v[k] = __ldcs(src + threadIdx.x + k * THREADS);
    #pragma unroll
    for (int k = 0; k < VEC_PER_THR; ++k)
        __stcs(dst + threadIdx.x + k * THREADS, v[k]);
}

extern "C" void kernel_launch(void* const* d_in, const int* in_sizes, int n_in,
                              void* d_out, int out_size)
{
    const float4* x     = (const float4*)d_in[0];
    const float4* cache = (const float4*)d_in[1];
    const int* running  = (const int*)d_in[2];
    const int* idx      = (const int*)d_in[3];
    float4* out         = (float4*)d_out;

    mlpcache_gather_kernel<<<N_RUNNING * ROWS_PER_SEQ, THREADS>>>(
        x, cache, running, idx, out);
}